// round 8
// baseline (speedup 1.0000x reference)
#include <cuda_runtime.h>
#include <cuda_bf16.h>
#include <cstdint>
#include <math.h>

#define BATCH 8192
#define EDIM  256
#define HDIM  50
#define N_INNER 31
#define N_LEAF  32

// ---------------------------------------------------------------------------
// Device scratch
// ---------------------------------------------------------------------------
__device__ float g_pR[N_INNER * BATCH];
__device__ float g_yleaf[N_LEAF * BATCH];

__device__ __nv_bfloat16 g_xh[BATCH * EDIM];
__device__ __nv_bfloat16 g_xl[BATCH * EDIM];
__device__ __nv_bfloat16 g_e0h[BATCH * EDIM];
__device__ __nv_bfloat16 g_e0l[BATCH * EDIM];
__device__ __nv_bfloat16 g_e1h[BATCH * EDIM];
__device__ __nv_bfloat16 g_e1l[BATCH * EDIM];
__device__ __nv_bfloat16 g_wth[36 * 65536];
__device__ __nv_bfloat16 g_wtl[36 * 65536];
__device__ __nv_bfloat16 g_w1th[N_INNER * 64 * 256];
__device__ __nv_bfloat16 g_w1tl[N_INNER * 64 * 256];
__device__ __nv_bfloat16 g_wwth[N_INNER * 256 * 64];
__device__ __nv_bfloat16 g_wwtl[N_INNER * 256 * 64];

// ---------------------------------------------------------------------------
// Helpers
// ---------------------------------------------------------------------------
__device__ __forceinline__ uint32_t smem_u32(const void* p) {
    uint32_t a;
    asm("{ .reg .u64 t; cvta.to.shared.u64 t, %1; cvt.u32.u64 %0, t; }" : "=r"(a) : "l"(p));
    return a;
}
#define CP_ASYNC16(dst, src) \
    asm volatile("cp.async.cg.shared.global [%0], [%1], 16;" :: "r"(dst), "l"(src) : "memory")
#define CP_COMMIT() asm volatile("cp.async.commit_group;" ::: "memory")
#define CP_WAIT2()  asm volatile("cp.async.wait_group 2;" ::: "memory")
#define CP_WAIT1()  asm volatile("cp.async.wait_group 1;" ::: "memory")
#define CP_WAIT0()  asm volatile("cp.async.wait_group 0;" ::: "memory")

#define LDSM4(r, addr) \
    asm volatile("ldmatrix.sync.aligned.m8n8.x4.shared.b16 {%0,%1,%2,%3}, [%4];" \
        : "=r"((r)[0]), "=r"((r)[1]), "=r"((r)[2]), "=r"((r)[3]) : "r"(addr))

__device__ __forceinline__ void mma_bf16(float* c, const uint32_t* a, const uint32_t* b) {
    asm volatile(
        "mma.sync.aligned.m16n8k16.row.col.f32.bf16.bf16.f32 "
        "{%0,%1,%2,%3}, {%4,%5,%6,%7}, {%8,%9}, {%0,%1,%2,%3};"
        : "+f"(c[0]), "+f"(c[1]), "+f"(c[2]), "+f"(c[3])
        : "r"(a[0]), "r"(a[1]), "r"(a[2]), "r"(a[3]), "r"(b[0]), "r"(b[1]));
}

__device__ __forceinline__ void split2(float a, float b, uint32_t& hi, uint32_t& lo) {
    __nv_bfloat16 h0 = __float2bfloat16(a), h1 = __float2bfloat16(b);
    __nv_bfloat16 l0 = __float2bfloat16(a - __bfloat162float(h0));
    __nv_bfloat16 l1 = __float2bfloat16(b - __bfloat162float(h1));
    __nv_bfloat16 hh[2] = {h0, h1}, ll[2] = {l0, l1};
    hi = *(uint32_t*)hh;
    lo = *(uint32_t*)ll;
}

// ---------------------------------------------------------------------------
// Mega-prep (unchanged from r7)
// ---------------------------------------------------------------------------
#define PR_X   2048
#define PR_W1  (PR_X + 1984)
#define PR_WW  (PR_W1 + 1984)
#define PR_Z   (PR_WW + 256)
#define PR_WT  (PR_Z + 36 * 64)

__global__ __launch_bounds__(256) void prep_all_kernel(
    const float* __restrict__ x, __nv_bfloat16* __restrict__ xh,
    __nv_bfloat16* __restrict__ xl,
    const float* __restrict__ W1, __nv_bfloat16* __restrict__ w1h,
    __nv_bfloat16* __restrict__ w1l,
    const float* __restrict__ Ww, __nv_bfloat16* __restrict__ wwh,
    __nv_bfloat16* __restrict__ wwl,
    float* __restrict__ yl,
    const float* __restrict__ encW, const float* __restrict__ lfW,
    __nv_bfloat16* __restrict__ wth, __nv_bfloat16* __restrict__ wtl)
{
    const int bid = blockIdx.x;
    const int t = threadIdx.x;
    if (bid < PR_X) {
        int i = bid * 256 + t;
        float4 v = ((const float4*)x)[i];
        float f[4] = {v.x, v.y, v.z, v.w};
        __nv_bfloat16 h[4], l[4];
#pragma unroll
        for (int j = 0; j < 4; j++) {
            h[j] = __float2bfloat16(f[j]);
            l[j] = __float2bfloat16(f[j] - __bfloat162float(h[j]));
        }
        *(uint2*)(xh + 4 * (size_t)i) = *(uint2*)h;
        *(uint2*)(xl + 4 * (size_t)i) = *(uint2*)l;
    } else if (bid < PR_W1) {
        int idx = (bid - PR_X) * 256 + t;
        int k = idx & 255, j = (idx >> 8) & 63, n = idx >> 14;
        float v = (j < HDIM) ? W1[((size_t)n * 256 + k) * HDIM + j] : 0.f;
        __nv_bfloat16 h = __float2bfloat16(v);
        w1h[idx] = h;
        w1l[idx] = __float2bfloat16(v - __bfloat162float(h));
    } else if (bid < PR_WW) {
        int idx = (bid - PR_W1) * 256 + t;
        int j = idx & 63, d = (idx >> 6) & 255, n = idx >> 14;
        float v = (j < HDIM) ? Ww[((size_t)n * HDIM + j) * 256 + d] : 0.f;
        __nv_bfloat16 h = __float2bfloat16(v);
        wwh[idx] = h;
        wwl[idx] = __float2bfloat16(v - __bfloat162float(h));
    } else if (bid < PR_Z) {
        int i = (bid - PR_WW) * 256 + t;
        ((float4*)yl)[i] = make_float4(0.f, 0.f, 0.f, 0.f);
    } else {
        __shared__ float tt[32][33];
        const int rel = bid - PR_Z;
        const int mat = rel >> 6;
        const int sub = rel & 63;
        const int nb = (sub & 7) * 32, kb = (sub >> 3) * 32;
        const int tx = t & 31, ty = t >> 5;
        const float* src = (mat < 4) ? (encW + (size_t)mat * 65536)
                                     : (lfW + (size_t)(mat - 4) * 65536);
#pragma unroll
        for (int i = 0; i < 4; i++)
            tt[ty + 8 * i][tx] = src[(size_t)(kb + ty + 8 * i) * 256 + nb + tx];
        __syncthreads();
#pragma unroll
        for (int i = 0; i < 4; i++) {
            float v = tt[tx][ty + 8 * i];
            size_t idx = (size_t)mat * 65536 + (size_t)(nb + ty + 8 * i) * 256 + kb + tx;
            __nv_bfloat16 h = __float2bfloat16(v);
            wth[idx] = h;
            wtl[idx] = __float2bfloat16(v - __bfloat162float(h));
        }
    }
}

// ---------------------------------------------------------------------------
// Unified 512-thread GEMM, 1 CTA/SM, deep cp.async pipeline.
// MODE 0 (encoder): M=64, N=256, 4 stages. relu(C+bias) -> bf16 hi/lo.
// MODE 1 (leaf):    M=128, N=256, 3 stages. atomicAdd(yleaf, relu(C+b1).W2).
// ---------------------------------------------------------------------------
#define G0_STG 51200                 // A 64x80x2 + B 256x80x2
#define G1_STG 61440                 // A 128x80x2 + B 256x80x2
#define G0_SMEM (4 * G0_STG)
#define G1_SMEM (3 * G1_STG + 2048)

template <int MODE>
__global__ __launch_bounds__(512, 1) void gemm512_kernel(
    const __nv_bfloat16* __restrict__ Ahp, const __nv_bfloat16* __restrict__ Alp,
    const __nv_bfloat16* __restrict__ Bh, const __nv_bfloat16* __restrict__ Bl,
    const float* __restrict__ bias, const float* __restrict__ w2,
    __nv_bfloat16* __restrict__ oh, __nv_bfloat16* __restrict__ ol,
    float* __restrict__ yleaf)
{
    constexpr int TM   = MODE ? 128 : 64;
    constexpr int NSTG = MODE ? 3 : 4;
    constexpr int PRE  = MODE ? 2 : 3;
    constexpr int STG  = MODE ? G1_STG : G0_STG;
    constexpr int ALO  = TM * 80;          // A-lo offset within stage
    constexpr int BOFF = 2 * TM * 80;      // B-hi offset within stage
    constexpr int NF   = MODE ? 8 : 4;     // n-frags per warp

    extern __shared__ char smem[];
    const uint32_t sb = smem_u32(smem);
    const int tid = threadIdx.x;
    const int lane = tid & 31, w = tid >> 5;
    const int m0 = blockIdx.x * TM;
    const int mat = MODE ? blockIdx.y : 0;

    const int wm = MODE ? (w >> 2) * 32 : (w >> 3) * 32;
    const int wn = MODE ? (w & 3) * 64  : (w & 7) * 32;

    const __nv_bfloat16* bhp = Bh + (size_t)mat * 65536;
    const __nv_bfloat16* blp = Bl + (size_t)mat * 65536;

    float* s_bias = (float*)(smem + NSTG * STG);
    float* s_w2   = s_bias + 256;
    if (MODE == 1) {
        if (tid < 256)      s_bias[tid] = bias[(size_t)mat * 256 + tid];
        else                s_w2[tid - 256] = w2[(size_t)mat * 256 + tid - 256];
    }

    float c[2][NF][4];
#pragma unroll
    for (int mf = 0; mf < 2; mf++)
#pragma unroll
        for (int nf = 0; nf < NF; nf++)
#pragma unroll
            for (int q = 0; q < 4; q++) c[mf][nf][q] = 0.f;

    const int arow = (lane & 7) + ((lane >> 3) & 1) * 8;
    const int acol = (lane >> 4) * 8;
    const int brow = (lane & 7) + (lane >> 4) * 8;
    const int bcol = ((lane >> 3) & 1) * 8;

    auto issue = [&](int CI) {
        const int k0_ = CI * 32;
        const uint32_t st_ = sb + (CI % NSTG) * STG;
        if (tid < 256) {
            const int row = tid >> 2, u = tid & 3;
            uint32_t d = st_ + row * 80 + u * 16;
            size_t ga = (size_t)(m0 + row) * 256 + k0_ + u * 8;
            CP_ASYNC16(d, Ahp + ga);
            CP_ASYNC16(d + ALO, Alp + ga);
            if (MODE == 1) {
                d += 64 * 80;
                ga += (size_t)64 * 256;
                CP_ASYNC16(d, Ahp + ga);
                CP_ASYNC16(d + ALO, Alp + ga);
            }
        } else {
            const int t2 = tid - 256, u = t2 & 3, r0_ = t2 >> 2;
#pragma unroll
            for (int rep = 0; rep < 4; rep++) {
                const int row = r0_ + rep * 64;
                const uint32_t d = st_ + BOFF + row * 80 + u * 16;
                const size_t gb = (size_t)row * 256 + k0_ + u * 8;
                CP_ASYNC16(d, bhp + gb);
                CP_ASYNC16(d + 20480, blp + gb);
            }
        }
        CP_COMMIT();
    };

    issue(0);
    issue(1);
    if (MODE == 0) issue(2);

#pragma unroll 1
    for (int ci = 0; ci < 8; ci++) {
        const int pend = (PRE - 1 < 7 - ci) ? PRE - 1 : 7 - ci;
        if (pend == 2) CP_WAIT2();
        else if (pend == 1) CP_WAIT1();
        else CP_WAIT0();
        __syncthreads();
        if (ci + PRE < 8) issue(ci + PRE);

        const uint32_t st = sb + (ci % NSTG) * STG;
#pragma unroll
        for (int kk = 0; kk < 32; kk += 16) {
            uint32_t ah[2][4], al[2][4];
#pragma unroll
            for (int mf = 0; mf < 2; mf++) {
                const uint32_t addr = st + (wm + mf * 16 + arow) * 80 + (kk + acol) * 2;
                LDSM4(ah[mf], addr);
                LDSM4(al[mf], addr + ALO);
            }
#pragma unroll
            for (int np = 0; np < NF / 2; np++) {
                const uint32_t baddr = st + BOFF
                    + (wn + np * 16 + brow) * 80 + (kk + bcol) * 2;
                uint32_t rh[4], rl[4];
                LDSM4(rh, baddr);
                LDSM4(rl, baddr + 20480);
                uint32_t b0h[2] = {rh[0], rh[1]}, b1h[2] = {rh[2], rh[3]};
                uint32_t b0l[2] = {rl[0], rl[1]}, b1l[2] = {rl[2], rl[3]};
#pragma unroll
                for (int mf = 0; mf < 2; mf++) {
                    mma_bf16(c[mf][2 * np],     ah[mf], b0h);
                    mma_bf16(c[mf][2 * np],     ah[mf], b0l);
                    mma_bf16(c[mf][2 * np],     al[mf], b0h);
                    mma_bf16(c[mf][2 * np + 1], ah[mf], b1h);
                    mma_bf16(c[mf][2 * np + 1], ah[mf], b1l);
                    mma_bf16(c[mf][2 * np + 1], al[mf], b1h);
                }
            }
        }
    }

    const int erow = lane >> 2;
    const int ecol = (lane & 3) * 2;

    if (MODE == 0) {
#pragma unroll
        for (int mf = 0; mf < 2; mf++) {
            const int gr0 = m0 + wm + mf * 16 + erow;
#pragma unroll
            for (int nf = 0; nf < NF; nf++) {
                const int gc = wn + nf * 8 + ecol;
                float2 bb = *(const float2*)&bias[gc];
                float v00 = fmaxf(c[mf][nf][0] + bb.x, 0.f);
                float v01 = fmaxf(c[mf][nf][1] + bb.y, 0.f);
                float v10 = fmaxf(c[mf][nf][2] + bb.x, 0.f);
                float v11 = fmaxf(c[mf][nf][3] + bb.y, 0.f);
                const size_t i0 = (size_t)gr0 * 256 + gc;
                const size_t i1 = (size_t)(gr0 + 8) * 256 + gc;
                uint32_t h0, l0, h1, l1;
                split2(v00, v01, h0, l0);
                split2(v10, v11, h1, l1);
                *(uint32_t*)(oh + i0) = h0;
                *(uint32_t*)(oh + i1) = h1;
                *(uint32_t*)(ol + i0) = l0;
                *(uint32_t*)(ol + i1) = l1;
            }
        }
    } else {
        float part[2][2] = {{0.f, 0.f}, {0.f, 0.f}};
#pragma unroll
        for (int mf = 0; mf < 2; mf++)
#pragma unroll
            for (int nf = 0; nf < NF; nf++) {
                const int lc = wn + nf * 8 + ecol;
                const float b0s = s_bias[lc], b1s = s_bias[lc + 1];
                const float w0 = s_w2[lc], w1 = s_w2[lc + 1];
                part[mf][0] = fmaf(fmaxf(c[mf][nf][0] + b0s, 0.f), w0, part[mf][0]);
                part[mf][0] = fmaf(fmaxf(c[mf][nf][1] + b1s, 0.f), w1, part[mf][0]);
                part[mf][1] = fmaf(fmaxf(c[mf][nf][2] + b0s, 0.f), w0, part[mf][1]);
                part[mf][1] = fmaf(fmaxf(c[mf][nf][3] + b1s, 0.f), w1, part[mf][1]);
            }
#pragma unroll
        for (int mf = 0; mf < 2; mf++)
#pragma unroll
            for (int h = 0; h < 2; h++) {
                part[mf][h] += __shfl_xor_sync(0xffffffffu, part[mf][h], 1);
                part[mf][h] += __shfl_xor_sync(0xffffffffu, part[mf][h], 2);
            }
        if ((lane & 3) == 0) {
#pragma unroll
            for (int mf = 0; mf < 2; mf++)
#pragma unroll
                for (int h = 0; h < 2; h++) {
                    const int row = m0 + wm + mf * 16 + h * 8 + erow;
                    atomicAdd(&yleaf[(size_t)mat * BATCH + row], part[mf][h]);
                }
        }
    }
}

// ---------------------------------------------------------------------------
// Inner-node kernel (r6 proven, unchanged)
// ---------------------------------------------------------------------------
#define IA_SZ  20480
#define IB_SZ  24576
#define IN_HH  73728
#define IN_HL  82944
#define IN_RED 92160
#define IN_WBS 93696
#define IN_WBTS 93952
#define IN_SMEM 94208

__global__ __launch_bounds__(256, 2) void inner_mma_kernel(
    const __nv_bfloat16* __restrict__ eh, const __nv_bfloat16* __restrict__ el,
    const __nv_bfloat16* __restrict__ w1h, const __nv_bfloat16* __restrict__ w1l,
    const __nv_bfloat16* __restrict__ wwh, const __nv_bfloat16* __restrict__ wwl,
    const float* __restrict__ x, const float* __restrict__ b1,
    const float* __restrict__ bw, const float* __restrict__ Wb,
    const float* __restrict__ bb, const float* __restrict__ Wbt,
    const float* __restrict__ bbt, float* __restrict__ pR)
{
    extern __shared__ char smem[];
    const uint32_t sb = smem_u32(smem);
    const int tid = threadIdx.x, lane = tid & 31, w = tid >> 5;
    const int n = blockIdx.y, m0 = blockIdx.x * 64;

    float* sWb  = (float*)(smem + IN_WBS);
    float* sWbt = (float*)(smem + IN_WBTS);
    if (tid < HDIM)          sWb[tid] = Wb[n * HDIM + tid];
    else if (tid < 2 * HDIM) sWbt[tid - HDIM] = Wbt[n * HDIM + tid - HDIM];

    const int crow = tid >> 2, cu = tid & 3;
    const __nv_bfloat16* w1hp = w1h + (size_t)n * 64 * 256;
    const __nv_bfloat16* w1lp = w1l + (size_t)n * 64 * 256;
    const __nv_bfloat16* wwhp = wwh + (size_t)n * 256 * 64;
    const __nv_bfloat16* wwlp = wwl + (size_t)n * 256 * 64;

#define IN_ISSUE(CI) do {                                           \
    const int k0_ = (CI) * 32;                                      \
    const uint32_t st_ = sb + ((CI) % 3) * IA_SZ;                   \
    const uint32_t d = st_ + crow * 80 + cu * 16;                   \
    const size_t ga = (size_t)(m0 + crow) * 256 + k0_ + cu * 8;     \
    const size_t gw = (size_t)crow * 256 + k0_ + cu * 8;            \
    CP_ASYNC16(d,         eh + ga);                                 \
    CP_ASYNC16(d + 5120,  el + ga);                                 \
    CP_ASYNC16(d + 10240, w1hp + gw);                               \
    CP_ASYNC16(d + 15360, w1lp + gw);                               \
    CP_COMMIT();                                                    \
} while (0)

    const int arow = (lane & 7) + ((lane >> 3) & 1) * 8;
    const int acol = (lane >> 4) * 8;
    const int brow = (lane & 7) + (lane >> 4) * 8;
    const int bcol = ((lane >> 3) & 1) * 8;

    const int wmA = (w >> 1) * 16, wnA = (w & 1) * 32;
    float accA[4][4];
#pragma unroll
    for (int i = 0; i < 4; i++)
#pragma unroll
        for (int q = 0; q < 4; q++) accA[i][q] = 0.f;

    IN_ISSUE(0);
    IN_ISSUE(1);

#pragma unroll 1
    for (int ci = 0; ci < 8; ci++) {
        if (ci < 7) CP_WAIT1(); else CP_WAIT0();
        __syncthreads();
        if (ci < 6) IN_ISSUE(ci + 2);

        const uint32_t st = sb + (ci % 3) * IA_SZ;
#pragma unroll
        for (int kk = 0; kk < 32; kk += 16) {
            uint32_t ah[4], al[4];
            const uint32_t aaddr = st + (wmA + arow) * 80 + (kk + acol) * 2;
            LDSM4(ah, aaddr);
            LDSM4(al, aaddr + 5120);
            uint32_t bh[4][2], bl[4][2];
#pragma unroll
            for (int g = 0; g < 2; g++) {
                const uint32_t baddr = st + 10240
                    + (wnA + g * 16 + brow) * 80 + (kk + bcol) * 2;
                uint32_t r[4];
                LDSM4(r, baddr);
                bh[2 * g][0] = r[0]; bh[2 * g][1] = r[1];
                bh[2 * g + 1][0] = r[2]; bh[2 * g + 1][1] = r[3];
                LDSM4(r, baddr + 5120);
                bl[2 * g][0] = r[0]; bl[2 * g][1] = r[1];
                bl[2 * g + 1][0] = r[2]; bl[2 * g + 1][1] = r[3];
            }
#pragma unroll
            for (int nf = 0; nf < 4; nf++) {
                mma_bf16(accA[nf], ah, bh[nf]);
                mma_bf16(accA[nf], ah, bl[nf]);
                mma_bf16(accA[nf], al, bh[nf]);
            }
        }
    }
#undef IN_ISSUE

    {
        const int r0 = wmA + (lane >> 2);
#pragma unroll
        for (int nf = 0; nf < 4; nf++) {
            const int col = wnA + nf * 8 + (lane & 3) * 2;
            const float bb0 = (col < HDIM)     ? b1[n * HDIM + col]     : 0.f;
            const float bb1 = (col + 1 < HDIM) ? b1[n * HDIM + col + 1] : 0.f;
            float v00 = fmaxf(accA[nf][0] + bb0, 0.f);
            float v01 = fmaxf(accA[nf][1] + bb1, 0.f);
            float v10 = fmaxf(accA[nf][2] + bb0, 0.f);
            float v11 = fmaxf(accA[nf][3] + bb1, 0.f);
            uint32_t h0, l0, h1, l1;
            split2(v00, v01, h0, l0);
            split2(v10, v11, h1, l1);
            *(uint32_t*)(smem + IN_HH + r0 * 144 + col * 2) = h0;
            *(uint32_t*)(smem + IN_HL + r0 * 144 + col * 2) = l0;
            *(uint32_t*)(smem + IN_HH + (r0 + 8) * 144 + col * 2) = h1;
            *(uint32_t*)(smem + IN_HL + (r0 + 8) * 144 + col * 2) = l1;
        }
    }
    __syncthreads();

#define IN_ISSUE_B(KK) do {                                         \
    const uint32_t st_ = sb + ((KK) % 3) * IB_SZ;                   \
    const uint32_t d = st_ + tid * 48;                              \
    const size_t g = (size_t)tid * 64 + (KK) * 16;                  \
    CP_ASYNC16(d,          wwhp + g);                               \
    CP_ASYNC16(d + 16,     wwhp + g + 8);                           \
    CP_ASYNC16(d + 12288,      wwlp + g);                           \
    CP_ASYNC16(d + 12288 + 16, wwlp + g + 8);                       \
    CP_COMMIT();                                                    \
} while (0)

    const int wmB = (w >> 1) * 16, wnB = (w & 1) * 128;
    float z[16][4];
#pragma unroll
    for (int nf = 0; nf < 16; nf++)
#pragma unroll
        for (int q = 0; q < 4; q++) z[nf][q] = 0.f;

    IN_ISSUE_B(0);
    IN_ISSUE_B(1);

#pragma unroll 1
    for (int kk = 0; kk < 4; kk++) {
        if (kk < 3) CP_WAIT1(); else CP_WAIT0();
        __syncthreads();
        if (kk < 2) IN_ISSUE_B(kk + 2);

        const uint32_t st = sb + (kk % 3) * IB_SZ;
        uint32_t ah[4], al[4];
        const uint32_t aaddr = sb + IN_HH + (wmB + arow) * 144 + (kk * 16 + acol) * 2;
        LDSM4(ah, aaddr);
        LDSM4(al, aaddr + (IN_HL - IN_HH));
#pragma unroll
        for (int g = 0; g < 8; g++) {
            const uint32_t baddr = st + (wnB + g * 16 + brow) * 48 + bcol * 2;
            uint32_t rh[4], rl[4];
            LDSM4(rh, baddr);
            LDSM4(rl, baddr + 12288);
            uint32_t b0h[2] = {rh[0], rh[1]}, b1h[2] = {rh[2], rh[3]};
            uint32_t b0l[2] = {rl[0], rl[1]}, b1l[2] = {rl[2], rl[3]};
            mma_bf16(z[2 * g],     ah, b0h);
            mma_bf16(z[2 * g],     ah, b0l);
            mma_bf16(z[2 * g],     al, b0h);
            mma_bf16(z[2 * g + 1], ah, b1h);
            mma_bf16(z[2 * g + 1], ah, b1l);
            mma_bf16(z[2 * g + 1], al, b1h);
        }
    }
#undef IN_ISSUE_B

    float* redmax = (float*)(smem + IN_RED);
    float* redse  = redmax + 128;
    float* redsx  = redse + 128;

    const int r0 = wmB + (lane >> 2), r1 = r0 + 8;
    float mx0 = -1e30f, mx1 = -1e30f;
#pragma unroll
    for (int nf = 0; nf < 16; nf++) {
        const int col = wnB + nf * 8 + (lane & 3) * 2;
        float2 bwv = *(const float2*)&bw[n * 256 + col];
        z[nf][0] += bwv.x; z[nf][1] += bwv.y;
        z[nf][2] += bwv.x; z[nf][3] += bwv.y;
        mx0 = fmaxf(mx0, fmaxf(z[nf][0], z[nf][1]));
        mx1 = fmaxf(mx1, fmaxf(z[nf][2], z[nf][3]));
    }
    mx0 = fmaxf(mx0, __shfl_xor_sync(0xffffffffu, mx0, 1));
    mx0 = fmaxf(mx0, __shfl_xor_sync(0xffffffffu, mx0, 2));
    mx1 = fmaxf(mx1, __shfl_xor_sync(0xffffffffu, mx1, 1));
    mx1 = fmaxf(mx1, __shfl_xor_sync(0xffffffffu, mx1, 2));
    if ((lane & 3) == 0) {
        redmax[(w & 1) * 64 + r0] = mx0;
        redmax[(w & 1) * 64 + r1] = mx1;
    }
    __syncthreads();
    mx0 = fmaxf(redmax[r0], redmax[64 + r0]);
    mx1 = fmaxf(redmax[r1], redmax[64 + r1]);

    float se0 = 0.f, sx0 = 0.f, se1 = 0.f, sx1 = 0.f;
    const float* x0 = x + (size_t)(m0 + r0) * 256;
    const float* x1 = x + (size_t)(m0 + r1) * 256;
#pragma unroll
    for (int nf = 0; nf < 16; nf++) {
        const int col = wnB + nf * 8 + (lane & 3) * 2;
        float2 xv0 = *(const float2*)&x0[col];
        float2 xv1 = *(const float2*)&x1[col];
        float e;
        e = __expf(z[nf][0] - mx0); se0 += e; sx0 = fmaf(e, xv0.x, sx0);
        e = __expf(z[nf][1] - mx0); se0 += e; sx0 = fmaf(e, xv0.y, sx0);
        e = __expf(z[nf][2] - mx1); se1 += e; sx1 = fmaf(e, xv1.x, sx1);
        e = __expf(z[nf][3] - mx1); se1 += e; sx1 = fmaf(e, xv1.y, sx1);
    }
#pragma unroll
    for (int off = 1; off <= 2; off <<= 1) {
        se0 += __shfl_xor_sync(0xffffffffu, se0, off);
        sx0 += __shfl_xor_sync(0xffffffffu, sx0, off);
        se1 += __shfl_xor_sync(0xffffffffu, se1, off);
        sx1 += __shfl_xor_sync(0xffffffffu, sx1, off);
    }
    if ((lane & 3) == 0) {
        redse[(w & 1) * 64 + r0] = se0; redse[(w & 1) * 64 + r1] = se1;
        redsx[(w & 1) * 64 + r0] = sx0; redsx[(w & 1) * 64 + r1] = sx1;
    }
    __syncthreads();

    if ((w & 1) == 0) {
        float pb0 = 0.f, pbt0 = 0.f, pb1 = 0.f, pbt1 = 0.f;
        for (int j = (lane & 3); j < HDIM; j += 4) {
            float h0 = __bfloat162float(*(const __nv_bfloat16*)(smem + IN_HH + r0 * 144 + j * 2))
                     + __bfloat162float(*(const __nv_bfloat16*)(smem + IN_HL + r0 * 144 + j * 2));
            float h1 = __bfloat162float(*(const __nv_bfloat16*)(smem + IN_HH + r1 * 144 + j * 2))
                     + __bfloat162float(*(const __nv_bfloat16*)(smem + IN_HL + r1 * 144 + j * 2));
            pb0  = fmaf(h0, sWb[j],  pb0);
            pbt0 = fmaf(h0, sWbt[j], pbt0);
            pb1  = fmaf(h1, sWb[j],  pb1);
            pbt1 = fmaf(h1, sWbt[j], pbt1);
        }
#pragma unroll
        for (int off = 1; off <= 2; off <<= 1) {
            pb0  += __shfl_xor_sync(0xffffffffu, pb0, off);
            pbt0 += __shfl_xor_sync(0xffffffffu, pbt0, off);
            pb1  += __shfl_xor_sync(0xffffffffu, pb1, off);
            pbt1 += __shfl_xor_sync(0xffffffffu, pbt1, off);
        }
        if ((lane & 3) == 0) {
            const float bbn = bb[n], bbtn = bbt[n];
            float seA = redse[r0] + redse[64 + r0];
            float sxA = redsx[r0] + redsx[64 + r0];
            float val = (pbt0 + bbtn) * (sxA / seA + pb0 + bbn);
            pR[(size_t)n * BATCH + m0 + r0] = 1.f / (1.f + __expf(-val));
            seA = redse[r1] + redse[64 + r1];
            sxA = redsx[r1] + redsx[64 + r1];
            val = (pbt1 + bbtn) * (sxA / seA + pb1 + bbn);
            pR[(size_t)n * BATCH + m0 + r1] = 1.f / (1.f + __expf(-val));
        }
    }
}

// ---------------------------------------------------------------------------
// Combine
// ---------------------------------------------------------------------------
__global__ __launch_bounds__(256) void combine_kernel(
    const float* __restrict__ pR, const float* __restrict__ yl,
    const float* __restrict__ b2, float* __restrict__ out)
{
    const int b = blockIdx.x * 256 + threadIdx.x;
    float p[N_INNER];
#pragma unroll
    for (int i = 0; i < N_INNER; i++) p[i] = pR[(size_t)i * BATCH + b];

    float prob[N_LEAF];
    prob[0] = 1.f;
#pragma unroll
    for (int lev = 0; lev < 5; lev++) {
        const int cnt = 1 << lev;
        const int off = cnt - 1;
#pragma unroll
        for (int i = N_LEAF - 1; i >= 0; i--) {
            if (i < cnt) {
                float pr   = p[off + i];
                float base = prob[i];
                prob[2 * i]     = base * (1.f - pr);
                prob[2 * i + 1] = base * pr;
            }
        }
    }
    float acc = 0.f;
#pragma unroll
    for (int l = 0; l < N_LEAF; l++)
        acc = fmaf(prob[l], yl[(size_t)l * BATCH + b] + b2[l], acc);
    out[b] = acc;
}

// ---------------------------------------------------------------------------
extern "C" void kernel_launch(void* const* d_in, const int* in_sizes, int n_in,
                              void* d_out, int out_size)
{
    const float* x       = (const float*)d_in[0];
    const float* enc_W   = (const float*)d_in[1];
    const float* enc_b   = (const float*)d_in[2];
    const float* in_W1   = (const float*)d_in[3];
    const float* in_b1   = (const float*)d_in[4];
    const float* in_Ww   = (const float*)d_in[5];
    const float* in_bw   = (const float*)d_in[6];
    const float* in_Wb   = (const float*)d_in[7];
    const float* in_bb   = (const float*)d_in[8];
    const float* in_Wbt  = (const float*)d_in[9];
    const float* in_bbt  = (const float*)d_in[10];
    const float* lf_W1   = (const float*)d_in[11];
    const float* lf_b1   = (const float*)d_in[12];
    const float* lf_W2   = (const float*)d_in[13];
    const float* lf_b2   = (const float*)d_in[14];
    float* out = (float*)d_out;

    float *pR, *yl;
    __nv_bfloat16 *xh, *xl, *e0h, *e0l, *e1h, *e1l, *wth, *wtl;
    __nv_bfloat16 *w1th, *w1tl, *wwth, *wwtl;
    cudaGetSymbolAddress((void**)&pR,  g_pR);
    cudaGetSymbolAddress((void**)&yl,  g_yleaf);
    cudaGetSymbolAddress((void**)&xh,  g_xh);
    cudaGetSymbolAddress((void**)&xl,  g_xl);
    cudaGetSymbolAddress((void**)&e0h, g_e0h);
    cudaGetSymbolAddress((void**)&e0l, g_e0l);
    cudaGetSymbolAddress((void**)&e1h, g_e1h);
    cudaGetSymbolAddress((void**)&e1l, g_e1l);
    cudaGetSymbolAddress((void**)&wth, g_wth);
    cudaGetSymbolAddress((void**)&wtl, g_wtl);
    cudaGetSymbolAddress((void**)&w1th, g_w1th);
    cudaGetSymbolAddress((void**)&w1tl, g_w1tl);
    cudaGetSymbolAddress((void**)&wwth, g_wwth);
    cudaGetSymbolAddress((void**)&wwtl, g_wwtl);

    cudaFuncSetAttribute(gemm512_kernel<0>, cudaFuncAttributeMaxDynamicSharedMemorySize, G0_SMEM);
    cudaFuncSetAttribute(gemm512_kernel<1>, cudaFuncAttributeMaxDynamicSharedMemorySize, G1_SMEM);
    cudaFuncSetAttribute(inner_mma_kernel,  cudaFuncAttributeMaxDynamicSharedMemorySize, IN_SMEM);

    // 1) prep
    prep_all_kernel<<<PR_WT, 256>>>(x, xh, xl, in_W1, w1th, w1tl,
                                    in_Ww, wwth, wwtl, yl,
                                    enc_W, lf_W1, wth, wtl);

    // 2-5) encoder (M=64, N=256, 4-stage, grid 128, 512 thr)
    gemm512_kernel<0><<<128, 512, G0_SMEM>>>(xh, xl, wth, wtl,
        enc_b, nullptr, e0h, e0l, nullptr);
    gemm512_kernel<0><<<128, 512, G0_SMEM>>>(e0h, e0l, wth + 65536, wtl + 65536,
        enc_b + 256, nullptr, e1h, e1l, nullptr);
    gemm512_kernel<0><<<128, 512, G0_SMEM>>>(e1h, e1l, wth + 2 * 65536, wtl + 2 * 65536,
        enc_b + 512, nullptr, e0h, e0l, nullptr);
    gemm512_kernel<0><<<128, 512, G0_SMEM>>>(e0h, e0l, wth + 3 * 65536, wtl + 3 * 65536,
        enc_b + 768, nullptr, e1h, e1l, nullptr);

    // 6) leaves (M=128, N=256, 3-stage, grid 64x32) — profiled launch
    gemm512_kernel<1><<<dim3(64, N_LEAF), 512, G1_SMEM>>>(
        e1h, e1l, wth + 4 * 65536, wtl + 4 * 65536,
        lf_b1, lf_W2, nullptr, nullptr, yl);

    // 7) inner gates
    inner_mma_kernel<<<dim3(BATCH / 64, N_INNER), 256, IN_SMEM>>>(
        e1h, e1l, w1th, w1tl, wwth, wwtl,
        x, in_b1, in_bw, in_Wb, in_bb, in_Wbt, in_bbt, pR);

    // 8) combine
    combine_kernel<<<BATCH / 256, 256>>>(pR, yl, lf_b2, out);
}